// round 14
// baseline (speedup 1.0000x reference)
#include <cuda_runtime.h>
#include <cuda_fp16.h>
#include <cstdint>

// ---------------------------------------------------------------------------
// MultiScaleRoIAlign3D — GB300, round 14
//   ONE persistent kernel, 1184 co-resident blocks, device grid barrier.
//   Phase A: per-box setup + feat1-3 transpose
//   Phase B: feat0 transpose tiles INTERLEAVED with lvl>=1 main units
//   Phase C: lvl0 main units
//   Main/setup math identical to round 12 (rel_err preserved exactly).
// ---------------------------------------------------------------------------

#define NCELLS 343
#define NB 1184            // 148 SMs x 8 blocks, all co-resident

__device__ __half  g_featT[19169280];  // 64ch * (64^3+32^3+16^3+8^3), NDHWC fp16
__device__ int4    g_toff[256][21];
__device__ uint4   g_twh[256][21];
__device__ int     g_cnt[256][21];
__device__ int     g_bbase[256];
__device__ int     g_lvl[256];
__device__ unsigned g_bar;             // grid barrier counter (memset to 0 per launch)

static __device__ __forceinline__ unsigned pack_bcast_h2(float w) {
    __half h = __float2half_rn(w);
    unsigned u = (unsigned)__half_as_ushort(h);
    return u | (u << 16);
}
static __device__ __forceinline__ __half2 u2h2(unsigned u) {
    return *(const __half2*)&u;
}

// ---------------------------- grid barrier ---------------------------------
static __device__ __forceinline__ void grid_barrier(unsigned target) {
    __syncthreads();
    if (threadIdx.x == 0) {
        __threadfence();                       // release my writes
        atomicAdd(&g_bar, 1u);
        while (*(volatile unsigned*)&g_bar < target) __nanosleep(64);
    }
    __syncthreads();
}

// ----------------------------- setup unit ----------------------------------
// one thread per (box, axis, o)
static __device__ __noinline__ void setup_unit(const float* __restrict__ boxes,
                                               int u, int N)
{
    if (u >= N * 21) return;
    int n   = u / 21;
    int rem = u - n * 21;
    int d   = rem / 7;
    int o   = rem - d * 7;

    float bx[6];
#pragma unroll
    for (int q = 0; q < 6; ++q) bx[q] = boxes[n * 6 + q];

    float vol = (bx[3] - bx[0]) * (bx[4] - bx[1]) * (bx[5] - bx[2]);
    float s   = cbrtf(vol);
    float lf  = floorf(4.0f + log2f(s / 160.0f) + 1e-6f);
    lf = fminf(fmaxf(lf, 2.0f), 5.0f);
    int lvl = (int)lf - 2;
    int dim = 64 >> lvl;
    int base = (lvl == 0) ? 0 : (lvl == 1) ? 16777216 : (lvl == 2) ? 18874368 : 19136512;
    float scale = 0.25f / (float)(1 << lvl);
    if (rem == 0) { g_bbase[n] = base; g_lvl[n] = lvl; }

    int stride = (d == 0) ? dim * dim * 64 : (d == 1) ? dim * 64 : 64;
    float dimf = (float)dim;

    float st  = bx[d] * scale;
    float sz  = fmaxf(bx[3 + d] * scale - st, 1.0f);
    float bsz = sz * (1.0f / 7.0f);

    int id[4]; float wt[4]; int cnt = 0;
#pragma unroll
    for (int r = 0; r < 2; ++r) {
        float c = st + ((float)o + 0.25f + 0.5f * (float)r) * bsz;
        float valid = (c > -1.0f && c < dimf) ? 0.5f : 0.0f;
        float cc = fminf(fmaxf(c, 0.0f), dimf - 1.0f);
        int lo = (int)floorf(cc);
        int hi = min(lo + 1, dim - 1);
        float frac = cc - (float)lo;
        float wl = (1.0f - frac) * valid;
        float wh = frac * valid;
        if (wl != 0.0f) {
            bool m = false;
            for (int k = 0; k < cnt; ++k)
                if (id[k] == lo) { wt[k] += wl; m = true; break; }
            if (!m) { id[cnt] = lo; wt[cnt] = wl; cnt++; }
        }
        if (wh != 0.0f) {
            bool m = false;
            for (int k = 0; k < cnt; ++k)
                if (id[k] == hi) { wt[k] += wh; m = true; break; }
            if (!m) { id[cnt] = hi; wt[cnt] = wh; cnt++; }
        }
    }
    int4 off; uint4 w;
    off.x = (cnt > 0) ? id[0] * stride : 0;  w.x = (cnt > 0) ? pack_bcast_h2(wt[0]) : 0u;
    off.y = (cnt > 1) ? id[1] * stride : 0;  w.y = (cnt > 1) ? pack_bcast_h2(wt[1]) : 0u;
    off.z = (cnt > 2) ? id[2] * stride : 0;  w.z = (cnt > 2) ? pack_bcast_h2(wt[2]) : 0u;
    off.w = (cnt > 3) ? id[3] * stride : 0;  w.w = (cnt > 3) ? pack_bcast_h2(wt[3]) : 0u;
    g_toff[n][d * 7 + o] = off;
    g_twh[n][d * 7 + o]  = w;
    g_cnt[n][d * 7 + o]  = cnt;
}

// --------------- transpose tile: 32 cells x 64 ch, 128 threads -------------
static __device__ __forceinline__ void transpose_tile32(
    const float* __restrict__ in, __half* __restrict__ out,
    int ncells, int cellbase, int t)
{
    __shared__ float tile[32][65];
    float4 v[4];
#pragma unroll
    for (int i = 0; i < 4; ++i) {
        int idx = i * 128 + t;      // 0..511
        int c   = idx >> 3;         // channel 0..63
        int cq  = idx & 7;          // cell group of 4
        v[i] = *(const float4*)(in + c * ncells + cellbase + cq * 4);
    }
#pragma unroll
    for (int i = 0; i < 4; ++i) {
        int idx = i * 128 + t;
        int c   = idx >> 3;
        int cq  = idx & 7;
        tile[cq * 4 + 0][c] = v[i].x;
        tile[cq * 4 + 1][c] = v[i].y;
        tile[cq * 4 + 2][c] = v[i].z;
        tile[cq * 4 + 3][c] = v[i].w;
    }
    __syncthreads();
#pragma unroll
    for (int i = 0; i < 2; ++i) {
        int idx  = i * 128 + t;     // 0..255
        int cell = idx >> 3;        // 0..31
        int g    = idx & 7;         // channel octet
        __half2 h[4];
#pragma unroll
        for (int q = 0; q < 4; ++q)
            h[q] = __floats2half2_rn(tile[cell][g * 8 + q * 2],
                                     tile[cell][g * 8 + q * 2 + 1]);
        *(uint4*)(out + (size_t)(cellbase + cell) * 64 + g * 8) = *(const uint4*)h;
    }
    __syncthreads();                // tile reuse across loop iterations
}

// ----------------------------- main unit -----------------------------------
// 128 threads = 8 channel-groups x 16 cells; unit = (box n, slice)
static __device__ __forceinline__ void main_unit(float* __restrict__ out,
                                                 int n, int slice)
{
    __shared__ int4   s_off[21];
    __shared__ uint4  s_wh[21];
    __shared__ int    s_cnt[21];
    __shared__ int    s_base;
    __shared__ float  s_tile[16][65];

    int t = threadIdx.x;

    if (t < 21) {
        s_off[t] = g_toff[n][t];
        s_wh[t]  = g_twh[n][t];
        s_cnt[t] = g_cnt[n][t];
    }
    if (t == 21) s_base = g_bbase[n];
    __syncthreads();

    int cx = t & 7;
    int cy = t >> 3;
    int cb = slice * 16;
    int cell = cb + cy;

    __half2 acc0 = __float2half2_rn(0.f), acc1 = acc0, acc2 = acc0, acc3 = acc0;

    if (cell < NCELLS) {
        int oz  = cell % 7;
        int rem = cell / 7;
        int oy  = rem % 7;
        int ox  = rem / 7;

        int nx = s_cnt[ox], ny = s_cnt[7 + oy];

        int4  xo4 = s_off[ox];      uint4 xw4 = s_wh[ox];
        int4  yo4 = s_off[7 + oy];  uint4 yw4 = s_wh[7 + oy];
        int4  zo4 = s_off[14 + oz]; uint4 zw4 = s_wh[14 + oz];
        __half2 zw0 = u2h2(zw4.x), zw1 = u2h2(zw4.y), zw2 = u2h2(zw4.z), zw3 = u2h2(zw4.w);

        const __half* fb = g_featT + s_base + cx * 8;

#pragma unroll
        for (int i = 0; i < 4; ++i) {
            if (i < nx) {
                int     xo = (i == 0) ? xo4.x : (i == 1) ? xo4.y : (i == 2) ? xo4.z : xo4.w;
                __half2 wx = u2h2((i == 0) ? xw4.x : (i == 1) ? xw4.y : (i == 2) ? xw4.z : xw4.w);
                const __half* px = fb + xo;
#pragma unroll
                for (int j = 0; j < 4; ++j) {
                    if (j < ny) {
                        int     yo = (j == 0) ? yo4.x : (j == 1) ? yo4.y : (j == 2) ? yo4.z : yo4.w;
                        __half2 wy = u2h2((j == 0) ? yw4.x : (j == 1) ? yw4.y : (j == 2) ? yw4.z : yw4.w);
                        const __half* pxy = px + yo;
                        __half2 wxy = __hmul2(wx, wy);

                        uint4 r0 = *(const uint4*)(pxy + zo4.x);
                        uint4 r1 = *(const uint4*)(pxy + zo4.y);
                        uint4 r2 = *(const uint4*)(pxy + zo4.z);
                        uint4 r3 = *(const uint4*)(pxy + zo4.w);

                        __half2 in0 = __float2half2_rn(0.f), in1 = in0, in2 = in0, in3 = in0;
                        in0 = __hfma2(u2h2(r0.x), zw0, in0);
                        in1 = __hfma2(u2h2(r0.y), zw0, in1);
                        in2 = __hfma2(u2h2(r0.z), zw0, in2);
                        in3 = __hfma2(u2h2(r0.w), zw0, in3);

                        in0 = __hfma2(u2h2(r1.x), zw1, in0);
                        in1 = __hfma2(u2h2(r1.y), zw1, in1);
                        in2 = __hfma2(u2h2(r1.z), zw1, in2);
                        in3 = __hfma2(u2h2(r1.w), zw1, in3);

                        in0 = __hfma2(u2h2(r2.x), zw2, in0);
                        in1 = __hfma2(u2h2(r2.y), zw2, in1);
                        in2 = __hfma2(u2h2(r2.z), zw2, in2);
                        in3 = __hfma2(u2h2(r2.w), zw2, in3);

                        in0 = __hfma2(u2h2(r3.x), zw3, in0);
                        in1 = __hfma2(u2h2(r3.y), zw3, in1);
                        in2 = __hfma2(u2h2(r3.z), zw3, in2);
                        in3 = __hfma2(u2h2(r3.w), zw3, in3);

                        acc0 = __hfma2(in0, wxy, acc0);
                        acc1 = __hfma2(in1, wxy, acc1);
                        acc2 = __hfma2(in2, wxy, acc2);
                        acc3 = __hfma2(in3, wxy, acc3);
                    }
                }
            }
        }
    }

    float2 r0 = __half22float2(acc0);
    float2 r1 = __half22float2(acc1);
    float2 r2 = __half22float2(acc2);
    float2 r3 = __half22float2(acc3);
    int cbase = cx * 8;
    s_tile[cy][cbase + 0] = r0.x; s_tile[cy][cbase + 1] = r0.y;
    s_tile[cy][cbase + 2] = r1.x; s_tile[cy][cbase + 3] = r1.y;
    s_tile[cy][cbase + 4] = r2.x; s_tile[cy][cbase + 5] = r2.y;
    s_tile[cy][cbase + 6] = r3.x; s_tile[cy][cbase + 7] = r3.y;
    __syncthreads();

    float* outn = out + n * 64 * NCELLS;
#pragma unroll
    for (int i = 0; i < 8; ++i) {
        int idx = t + i * 128;
        int c   = idx >> 4;
        int cl  = idx & 15;
        if (cb + cl < NCELLS)
            outn[c * NCELLS + cb + cl] = s_tile[cl][c];
    }
}

// --------------------------- persistent kernel -----------------------------
__global__ void __launch_bounds__(128, 8) fused_kernel(
    const float* __restrict__ f0, const float* __restrict__ f1,
    const float* __restrict__ f2, const float* __restrict__ f3,
    const float* __restrict__ boxes, float* __restrict__ out, int N)
{
    int bid = blockIdx.x;
    int t   = threadIdx.x;

    // ---------------- Phase A: setup + feat1-3 transpose -------------------
    int setupU = (N * 21 + 127) / 128;
    int unitsA = setupU + 1168;                 // 1024 + 128 + 16 transpose tiles
    for (int u = bid; u < unitsA; u += NB) {
        if (u < setupU) {
            setup_unit(boxes, u * 128 + t, N);
        } else {
            int b2 = u - setupU;
            if (b2 < 1024)      transpose_tile32(f1, g_featT + 16777216, 32768, b2 * 32, t);
            else if (b2 < 1152) transpose_tile32(f2, g_featT + 18874368, 4096, (b2 - 1024) * 32, t);
            else                transpose_tile32(f3, g_featT + 19136512, 512,  (b2 - 1152) * 32, t);
        }
    }
    grid_barrier(NB);

    // ------- Phase B: feat0 transpose (8192 tiles) || lvl>=1 main ----------
    int mainU  = N * 22;
    int pairU  = 2 * mainU;                     // interleave while both remain
    int totalB = 8192 + mainU;
    for (int u = bid; u < totalB; u += NB) {
        if (u < pairU) {
            if (u & 1) {
                int m = u >> 1;
                int n = m / 22;
                if (g_lvl[n] != 0) main_unit(out, n, m - n * 22);
            } else {
                transpose_tile32(f0, g_featT, 262144, (u >> 1) * 32, t);
            }
        } else {
            transpose_tile32(f0, g_featT, 262144, (mainU + (u - pairU)) * 32, t);
        }
    }
    grid_barrier(2 * NB);

    // ---------------- Phase C: lvl0 main units -----------------------------
    for (int m = bid; m < mainU; m += NB) {
        int n = m / 22;
        if (g_lvl[n] == 0) main_unit(out, n, m - n * 22);
    }
}

// ------------------------------ launcher -----------------------------------
extern "C" void kernel_launch(void* const* d_in, const int* in_sizes, int n_in,
                              void* d_out, int out_size)
{
    const float* f0    = (const float*)d_in[0];
    const float* f1    = (const float*)d_in[1];
    const float* f2    = (const float*)d_in[2];
    const float* f3    = (const float*)d_in[3];
    const float* boxes = (const float*)d_in[4];
    float* out = (float*)d_out;

    int N = in_sizes[4] / 6;
    if (N > 256) N = 256;

    void* bar_ptr = nullptr;
    cudaGetSymbolAddress(&bar_ptr, g_bar);
    cudaMemsetAsync(bar_ptr, 0, sizeof(unsigned));   // reset barrier each replay

    fused_kernel<<<NB, 128>>>(f0, f1, f2, f3, boxes, out, N);
}

// round 15
// speedup vs baseline: 1.6012x; 1.6012x over previous
#include <cuda_runtime.h>
#include <cuda_fp16.h>
#include <cstdint>

// ---------------------------------------------------------------------------
// MultiScaleRoIAlign3D — GB300, round 15
//   = round 12 (best structure) with main-kernel occupancy cap 8 -> 6
//     blocks/SM: ~85 regs/thread so ptxas keeps 2-3 groups of predicated
//     LDG.128s in flight (MLP up ~2x at 0.75x warps; latency-bound regime).
// ---------------------------------------------------------------------------

#define NCELLS 343

__device__ __half  g_featT[19169280];  // 64ch * (64^3+32^3+16^3+8^3), NDHWC fp16
__device__ int4    g_toff[256][21];    // premultiplied element offsets (pad = 0)
__device__ uint4   g_twh[256][21];     // merged weights as broadcast half2 (pad = 0)
__device__ int     g_cnt[256][21];     // tap counts
__device__ int     g_bbase[256];       // level base offset

#define NTRANS 4680

static __device__ __forceinline__ unsigned pack_bcast_h2(float w) {
    __half h = __float2half_rn(w);
    unsigned u = (unsigned)__half_as_ushort(h);
    return u | (u << 16);
}
static __device__ __forceinline__ __half2 u2h2(unsigned u) {
    return *(const __half2*)&u;
}

// ------------------- fused transpose + setup kernel -----------------------
__global__ void __launch_bounds__(256) prep_kernel(
    const float* __restrict__ f0, const float* __restrict__ f1,
    const float* __restrict__ f2, const float* __restrict__ f3,
    const float* __restrict__ boxes, int N)
{
    int b = blockIdx.x;
    int t = threadIdx.x;

    if (b >= NTRANS) {
        // ---------------- setup: one thread per (box, axis) ----------------
        int nd = (b - NTRANS) * 256 + t;
        int n = nd / 3;
        int d = nd - 3 * n;
        if (n >= N) return;

        float bx[6];
#pragma unroll
        for (int q = 0; q < 6; ++q) bx[q] = boxes[n * 6 + q];

        float vol = (bx[3] - bx[0]) * (bx[4] - bx[1]) * (bx[5] - bx[2]);
        float s   = cbrtf(vol);
        float lf  = floorf(4.0f + log2f(s / 160.0f) + 1e-6f);
        lf = fminf(fmaxf(lf, 2.0f), 5.0f);
        int lvl = (int)lf - 2;
        int dim = 64 >> lvl;
        int base = (lvl == 0) ? 0 : (lvl == 1) ? 16777216 : (lvl == 2) ? 18874368 : 19136512;
        float scale = 0.25f / (float)(1 << lvl);
        if (d == 0) g_bbase[n] = base;

        int stride = (d == 0) ? dim * dim * 64 : (d == 1) ? dim * 64 : 64;
        float dimf = (float)dim;

        float st  = bx[d] * scale;
        float sz  = fmaxf(bx[3 + d] * scale - st, 1.0f);
        float bsz = sz * (1.0f / 7.0f);

        for (int o = 0; o < 7; ++o) {
            int id[4]; float wt[4]; int cnt = 0;
#pragma unroll
            for (int r = 0; r < 2; ++r) {
                float c = st + ((float)o + 0.25f + 0.5f * (float)r) * bsz;
                float valid = (c > -1.0f && c < dimf) ? 0.5f : 0.0f;
                float cc = fminf(fmaxf(c, 0.0f), dimf - 1.0f);
                int lo = (int)floorf(cc);
                int hi = min(lo + 1, dim - 1);
                float frac = cc - (float)lo;
                float wl = (1.0f - frac) * valid;
                float wh = frac * valid;
                if (wl != 0.0f) {
                    bool m = false;
                    for (int k = 0; k < cnt; ++k)
                        if (id[k] == lo) { wt[k] += wl; m = true; break; }
                    if (!m) { id[cnt] = lo; wt[cnt] = wl; cnt++; }
                }
                if (wh != 0.0f) {
                    bool m = false;
                    for (int k = 0; k < cnt; ++k)
                        if (id[k] == hi) { wt[k] += wh; m = true; break; }
                    if (!m) { id[cnt] = hi; wt[cnt] = wh; cnt++; }
                }
            }
            int4 off; uint4 w;
            off.x = (cnt > 0) ? id[0] * stride : 0;  w.x = (cnt > 0) ? pack_bcast_h2(wt[0]) : 0u;
            off.y = (cnt > 1) ? id[1] * stride : 0;  w.y = (cnt > 1) ? pack_bcast_h2(wt[1]) : 0u;
            off.z = (cnt > 2) ? id[2] * stride : 0;  w.z = (cnt > 2) ? pack_bcast_h2(wt[2]) : 0u;
            off.w = (cnt > 3) ? id[3] * stride : 0;  w.w = (cnt > 3) ? pack_bcast_h2(wt[3]) : 0u;
            g_toff[n][d * 7 + o] = off;
            g_twh[n][d * 7 + o]  = w;
            g_cnt[n][d * 7 + o]  = cnt;
        }
        return;
    }

    // ------------- transpose + fp16 convert: 64 cells x 64 ch --------------
    __shared__ float tile[64][65];
    const float* in;
    __half* out;
    int ncells, cellbase;
    if (b < 4096)      { in = f0; out = g_featT;            ncells = 262144; cellbase = b * 64; }
    else if (b < 4608) { in = f1; out = g_featT + 16777216; ncells = 32768;  cellbase = (b - 4096) * 64; }
    else if (b < 4672) { in = f2; out = g_featT + 18874368; ncells = 4096;   cellbase = (b - 4608) * 64; }
    else               { in = f3; out = g_featT + 19136512; ncells = 512;    cellbase = (b - 4672) * 64; }

#pragma unroll
    for (int i = 0; i < 4; ++i) {
        int idx = i * 256 + t;      // 0..1023
        int c   = idx >> 4;         // channel 0..63
        int cq  = idx & 15;         // cell group of 4
        float4 v = *(const float4*)(in + c * ncells + cellbase + cq * 4);
        tile[cq * 4 + 0][c] = v.x;
        tile[cq * 4 + 1][c] = v.y;
        tile[cq * 4 + 2][c] = v.z;
        tile[cq * 4 + 3][c] = v.w;
    }
    __syncthreads();
#pragma unroll
    for (int i = 0; i < 2; ++i) {
        int idx  = i * 256 + t;     // 0..511
        int cell = idx >> 3;        // 0..63
        int g    = idx & 7;         // channel octet
        __half2 h[4];
#pragma unroll
        for (int q = 0; q < 4; ++q)
            h[q] = __floats2half2_rn(tile[cell][g * 8 + q * 2],
                                     tile[cell][g * 8 + q * 2 + 1]);
        *(uint4*)(out + (size_t)(cellbase + cell) * 64 + g * 8) = *(const uint4*)h;
    }
}

// --------------------------- main kernel ----------------------------------
// grid: (22, N)  — x = cell slice (fast), y = box. A wave covers all 22
// slices of ~54 boxes -> L2-resident working set + 22x tap reuse.
// block: 128 = 8 channel-groups (8 ch each) x 16 cells. 6 blocks/SM cap
// (~85 regs) -> more in-flight predicated LDG.128s per thread.
__global__ void __launch_bounds__(128, 6) roi_main_kernel(float* __restrict__ out)
{
    __shared__ int4   s_off[21];
    __shared__ uint4  s_wh[21];
    __shared__ int    s_cnt[21];
    __shared__ int    s_base;
    __shared__ float  s_tile[16][65];

    int n = blockIdx.y;
    int t = threadIdx.x;

    if (t < 21) {
        s_off[t] = g_toff[n][t];
        s_wh[t]  = g_twh[n][t];
        s_cnt[t] = g_cnt[n][t];
    }
    if (t == 21) s_base = g_bbase[n];
    __syncthreads();

    int cx = t & 7;        // channel group (8 channels)
    int cy = t >> 3;       // cell lane (16 per block)
    int cb = blockIdx.x * 16;
    int cell = cb + cy;

    __half2 acc0 = __float2half2_rn(0.f), acc1 = acc0, acc2 = acc0, acc3 = acc0;

    if (cell < NCELLS) {
        int oz  = cell % 7;
        int rem = cell / 7;
        int oy  = rem % 7;
        int ox  = rem / 7;

        int nx = s_cnt[ox], ny = s_cnt[7 + oy];

        // register-resident tap tables (no shared loads in hot loop)
        int4  xo4 = s_off[ox];      uint4 xw4 = s_wh[ox];
        int4  yo4 = s_off[7 + oy];  uint4 yw4 = s_wh[7 + oy];
        int4  zo4 = s_off[14 + oz]; uint4 zw4 = s_wh[14 + oz];
        __half2 zw0 = u2h2(zw4.x), zw1 = u2h2(zw4.y), zw2 = u2h2(zw4.z), zw3 = u2h2(zw4.w);

        const __half* fb = g_featT + s_base + cx * 8;

#pragma unroll
        for (int i = 0; i < 4; ++i) {
            if (i < nx) {
                int     xo = (i == 0) ? xo4.x : (i == 1) ? xo4.y : (i == 2) ? xo4.z : xo4.w;
                __half2 wx = u2h2((i == 0) ? xw4.x : (i == 1) ? xw4.y : (i == 2) ? xw4.z : xw4.w);
                const __half* px = fb + xo;
#pragma unroll
                for (int j = 0; j < 4; ++j) {
                    if (j < ny) {
                        int     yo = (j == 0) ? yo4.x : (j == 1) ? yo4.y : (j == 2) ? yo4.z : yo4.w;
                        __half2 wy = u2h2((j == 0) ? yw4.x : (j == 1) ? yw4.y : (j == 2) ? yw4.z : yw4.w);
                        const __half* pxy = px + yo;
                        __half2 wxy = __hmul2(wx, wy);

                        // unconditional z loads (zero-weight padding, offset 0)
                        uint4 r0 = *(const uint4*)(pxy + zo4.x);
                        uint4 r1 = *(const uint4*)(pxy + zo4.y);
                        uint4 r2 = *(const uint4*)(pxy + zo4.z);
                        uint4 r3 = *(const uint4*)(pxy + zo4.w);

                        __half2 in0 = __float2half2_rn(0.f), in1 = in0, in2 = in0, in3 = in0;
                        in0 = __hfma2(u2h2(r0.x), zw0, in0);
                        in1 = __hfma2(u2h2(r0.y), zw0, in1);
                        in2 = __hfma2(u2h2(r0.z), zw0, in2);
                        in3 = __hfma2(u2h2(r0.w), zw0, in3);

                        in0 = __hfma2(u2h2(r1.x), zw1, in0);
                        in1 = __hfma2(u2h2(r1.y), zw1, in1);
                        in2 = __hfma2(u2h2(r1.z), zw1, in2);
                        in3 = __hfma2(u2h2(r1.w), zw1, in3);

                        in0 = __hfma2(u2h2(r2.x), zw2, in0);
                        in1 = __hfma2(u2h2(r2.y), zw2, in1);
                        in2 = __hfma2(u2h2(r2.z), zw2, in2);
                        in3 = __hfma2(u2h2(r2.w), zw2, in3);

                        in0 = __hfma2(u2h2(r3.x), zw3, in0);
                        in1 = __hfma2(u2h2(r3.y), zw3, in1);
                        in2 = __hfma2(u2h2(r3.z), zw3, in2);
                        in3 = __hfma2(u2h2(r3.w), zw3, in3);

                        acc0 = __hfma2(in0, wxy, acc0);
                        acc1 = __hfma2(in1, wxy, acc1);
                        acc2 = __hfma2(in2, wxy, acc2);
                        acc3 = __hfma2(in3, wxy, acc3);
                    }
                }
            }
        }
    }

    // convert once, stage to smem, write coalesced (cells innermost)
    float2 r0 = __half22float2(acc0);
    float2 r1 = __half22float2(acc1);
    float2 r2 = __half22float2(acc2);
    float2 r3 = __half22float2(acc3);
    int cbase = cx * 8;
    s_tile[cy][cbase + 0] = r0.x; s_tile[cy][cbase + 1] = r0.y;
    s_tile[cy][cbase + 2] = r1.x; s_tile[cy][cbase + 3] = r1.y;
    s_tile[cy][cbase + 4] = r2.x; s_tile[cy][cbase + 5] = r2.y;
    s_tile[cy][cbase + 6] = r3.x; s_tile[cy][cbase + 7] = r3.y;
    __syncthreads();

    float* outn = out + n * 64 * NCELLS;
#pragma unroll
    for (int i = 0; i < 8; ++i) {
        int idx = t + i * 128;
        int c   = idx >> 4;
        int cl  = idx & 15;
        if (cb + cl < NCELLS)
            outn[c * NCELLS + cb + cl] = s_tile[cl][c];
    }
}

// ------------------------------ launcher -----------------------------------
extern "C" void kernel_launch(void* const* d_in, const int* in_sizes, int n_in,
                              void* d_out, int out_size)
{
    const float* f0    = (const float*)d_in[0];
    const float* f1    = (const float*)d_in[1];
    const float* f2    = (const float*)d_in[2];
    const float* f3    = (const float*)d_in[3];
    const float* boxes = (const float*)d_in[4];
    float* out = (float*)d_out;

    int N = in_sizes[4] / 6;
    if (N > 256) N = 256;

    int setup_blocks = (N * 3 + 255) / 256;
    prep_kernel<<<NTRANS + setup_blocks, 256>>>(f0, f1, f2, f3, boxes, N);
    roi_main_kernel<<<dim3(22, N), 128>>>(out);
}